// round 6
// baseline (speedup 1.0000x reference)
#include <cuda_runtime.h>
#include <cuda_fp16.h>
#include <cstdint>

// Problem constants
#define B_   16
#define S_   626
#define D_   768
#define H_   12
#define HD_  64
#define M_   (B_*S_)          // 10016
#define BH_  (B_*H_)          // 192
#define SM1_ (S_-1)           // 625
#define PSTR 644              // P row stride (floats)
#define QSTR 68               // Q/K tile row stride (floats)
#define VSTR 72               // V tile row stride
#define QT   32               // q-tile rows in fused_attn
#define KP   24               // half-precision tile k-stride (halves)

// Scratch (device globals; no cudaMalloc allowed)
__device__ float g_q[BH_*(size_t)S_*HD_];     // [b,h,s,hd]
__device__ float g_k[BH_*(size_t)S_*HD_];
__device__ float g_v[BH_*(size_t)S_*HD_];
__device__ float g_ctx[(size_t)M_*D_];        // [b,s, h*64+hd]
__device__ float g_contrib[BH_*S_];           // fixed scores col 0

// ---------------------------------------------------------------------------
// helpers
// ---------------------------------------------------------------------------
__device__ __forceinline__ uint32_t f2t(float x) {
    uint32_t r;
    asm("cvt.rna.tf32.f32 %0, %1;" : "=r"(r) : "f"(x));
    return r;
}

__device__ __forceinline__ void mma_tf32(float c[4],
    uint32_t a0, uint32_t a1, uint32_t a2, uint32_t a3,
    uint32_t b0, uint32_t b1)
{
    asm volatile(
        "mma.sync.aligned.m16n8k8.row.col.f32.tf32.tf32.f32 "
        "{%0,%1,%2,%3}, {%4,%5,%6,%7}, {%8,%9}, {%0,%1,%2,%3};"
        : "+f"(c[0]), "+f"(c[1]), "+f"(c[2]), "+f"(c[3])
        : "r"(a0), "r"(a1), "r"(a2), "r"(a3), "r"(b0), "r"(b1));
}

__device__ __forceinline__ void mma_fp16(float c[4],
    uint32_t a0, uint32_t a1, uint32_t a2, uint32_t a3,
    uint32_t b0, uint32_t b1)
{
    asm volatile(
        "mma.sync.aligned.m16n8k16.row.col.f32.f16.f16.f32 "
        "{%0,%1,%2,%3}, {%4,%5,%6,%7}, {%8,%9}, {%0,%1,%2,%3};"
        : "+f"(c[0]), "+f"(c[1]), "+f"(c[2]), "+f"(c[3])
        : "r"(a0), "r"(a1), "r"(a2), "r"(a3), "r"(b0), "r"(b1));
}

// ---------------------------------------------------------------------------
// Fused QKV projection (fp16 MMA m16n8k16): C[M,2304] = X @ [Wq|Wk|Wv] + bias.
// A tile [128][KP] halves ([m][k]); B tile [128][KP] halves ([n][k]).
// 128x128 block, BK=16, 256 threads, warp tile 64x32.
// ---------------------------------------------------------------------------
__global__ __launch_bounds__(256) void gemm_qkv(
    const float* __restrict__ X,
    const float* __restrict__ Wq, const float* __restrict__ bq,
    const float* __restrict__ Wk, const float* __restrict__ bk,
    const float* __restrict__ Wv, const float* __restrict__ bv)
{
    __shared__ __align__(16) __half As[128][KP];
    __shared__ __align__(16) __half Bs[128][KP];
    const int tid = threadIdx.x;
    const int m0  = blockIdx.x * 128;
    const int ng  = blockIdx.y * 128;
    const int mat = ng / D_;
    const int n0  = ng - mat * D_;
    const float* W    = (mat == 0) ? Wq : (mat == 1) ? Wk : Wv;
    const float* bias = (mat == 0) ? bq : (mat == 1) ? bk : bv;
    float* dst        = (mat == 0) ? g_q : (mat == 1) ? g_k : g_v;

    const int wid = tid >> 5, lane = tid & 31;
    const int gid = lane >> 2, tk = lane & 3;
    const int wm = (wid & 1) * 64;
    const int wn = (wid >> 1) * 32;

    float acc[4][4][4];
    #pragma unroll
    for (int mi = 0; mi < 4; mi++)
        #pragma unroll
        for (int ni = 0; ni < 4; ni++)
            #pragma unroll
            for (int r = 0; r < 4; r++) acc[mi][ni][r] = 0.f;

    for (int k0 = 0; k0 < D_; k0 += 16) {
        // A tile: 128 rows x 16 k (f32 -> half), [m][k]
        #pragma unroll
        for (int i = 0; i < 2; i++) {
            const int idx = tid + i * 256;
            const int row = idx >> 2, c4 = (idx & 3) << 2;
            float4 v = make_float4(0.f, 0.f, 0.f, 0.f);
            if (m0 + row < M_)
                v = *(const float4*)(X + (size_t)(m0 + row) * D_ + k0 + c4);
            *(__half2*)&As[row][c4]     = __floats2half2_rn(v.x, v.y);
            *(__half2*)&As[row][c4 + 2] = __floats2half2_rn(v.z, v.w);
        }
        // B tile: W[k][n] f32 -> Bs[n][k] half (transpose)
        #pragma unroll
        for (int i = 0; i < 2; i++) {
            const int idx = tid + i * 256;
            const int kr = idx & 15, n4 = (idx >> 4) << 2;
            float4 v = *(const float4*)(W + (size_t)(k0 + kr) * D_ + n0 + n4);
            Bs[n4 + 0][kr] = __float2half_rn(v.x);
            Bs[n4 + 1][kr] = __float2half_rn(v.y);
            Bs[n4 + 2][kr] = __float2half_rn(v.z);
            Bs[n4 + 3][kr] = __float2half_rn(v.w);
        }
        __syncthreads();

        uint32_t bf[4][2];
        #pragma unroll
        for (int ni = 0; ni < 4; ni++) {
            const int nb = wn + ni * 8 + gid;
            bf[ni][0] = *(const uint32_t*)&Bs[nb][2 * tk];
            bf[ni][1] = *(const uint32_t*)&Bs[nb][2 * tk + 8];
        }
        #pragma unroll
        for (int mi = 0; mi < 4; mi++) {
            const int am = wm + mi * 16;
            const uint32_t a0 = *(const uint32_t*)&As[am + gid    ][2 * tk];
            const uint32_t a1 = *(const uint32_t*)&As[am + gid + 8][2 * tk];
            const uint32_t a2 = *(const uint32_t*)&As[am + gid    ][2 * tk + 8];
            const uint32_t a3 = *(const uint32_t*)&As[am + gid + 8][2 * tk + 8];
            #pragma unroll
            for (int ni = 0; ni < 4; ni++)
                mma_fp16(acc[mi][ni], a0, a1, a2, a3, bf[ni][0], bf[ni][1]);
        }
        __syncthreads();
    }

    #pragma unroll
    for (int mi = 0; mi < 4; mi++) {
        #pragma unroll
        for (int ni = 0; ni < 4; ni++) {
            const int col = n0 + wn + ni * 8 + 2 * tk;
            const int h = col >> 6, hd = col & 63;
            const float b0v = bias[col], b1v = bias[col + 1];
            const int r0 = m0 + wm + mi * 16 + gid;
            const int r1 = r0 + 8;
            if (r0 < M_) {
                const int b = r0 / S_, s = r0 - b * S_;
                *(float2*)(dst + (((size_t)(b * H_ + h)) * S_ + s) * HD_ + hd) =
                    make_float2(acc[mi][ni][0] + b0v, acc[mi][ni][1] + b1v);
            }
            if (r1 < M_) {
                const int b = r1 / S_, s = r1 - b * S_;
                *(float2*)(dst + (((size_t)(b * H_ + h)) * S_ + s) * HD_ + hd) =
                    make_float2(acc[mi][ni][2] + b0v, acc[mi][ni][3] + b1v);
            }
        }
    }
}

// ---------------------------------------------------------------------------
// Output projection (fp16 MMA m16n8k16): out[M,768] = g_ctx @ Wo + bo
// ---------------------------------------------------------------------------
__global__ __launch_bounds__(256) void gemm_out(
    const float* __restrict__ W, const float* __restrict__ bias,
    float* __restrict__ out)
{
    __shared__ __align__(16) __half As[128][KP];
    __shared__ __align__(16) __half Bs[128][KP];
    const int tid = threadIdx.x;
    const int m0  = blockIdx.x * 128;
    const int n0  = blockIdx.y * 128;

    const int wid = tid >> 5, lane = tid & 31;
    const int gid = lane >> 2, tk = lane & 3;
    const int wm = (wid & 1) * 64;
    const int wn = (wid >> 1) * 32;

    float acc[4][4][4];
    #pragma unroll
    for (int mi = 0; mi < 4; mi++)
        #pragma unroll
        for (int ni = 0; ni < 4; ni++)
            #pragma unroll
            for (int r = 0; r < 4; r++) acc[mi][ni][r] = 0.f;

    for (int k0 = 0; k0 < D_; k0 += 16) {
        #pragma unroll
        for (int i = 0; i < 2; i++) {
            const int idx = tid + i * 256;
            const int row = idx >> 2, c4 = (idx & 3) << 2;
            float4 v = make_float4(0.f, 0.f, 0.f, 0.f);
            if (m0 + row < M_)
                v = *(const float4*)(g_ctx + (size_t)(m0 + row) * D_ + k0 + c4);
            *(__half2*)&As[row][c4]     = __floats2half2_rn(v.x, v.y);
            *(__half2*)&As[row][c4 + 2] = __floats2half2_rn(v.z, v.w);
        }
        #pragma unroll
        for (int i = 0; i < 2; i++) {
            const int idx = tid + i * 256;
            const int kr = idx & 15, n4 = (idx >> 4) << 2;
            float4 v = *(const float4*)(W + (size_t)(k0 + kr) * D_ + n0 + n4);
            Bs[n4 + 0][kr] = __float2half_rn(v.x);
            Bs[n4 + 1][kr] = __float2half_rn(v.y);
            Bs[n4 + 2][kr] = __float2half_rn(v.z);
            Bs[n4 + 3][kr] = __float2half_rn(v.w);
        }
        __syncthreads();

        uint32_t bf[4][2];
        #pragma unroll
        for (int ni = 0; ni < 4; ni++) {
            const int nb = wn + ni * 8 + gid;
            bf[ni][0] = *(const uint32_t*)&Bs[nb][2 * tk];
            bf[ni][1] = *(const uint32_t*)&Bs[nb][2 * tk + 8];
        }
        #pragma unroll
        for (int mi = 0; mi < 4; mi++) {
            const int am = wm + mi * 16;
            const uint32_t a0 = *(const uint32_t*)&As[am + gid    ][2 * tk];
            const uint32_t a1 = *(const uint32_t*)&As[am + gid + 8][2 * tk];
            const uint32_t a2 = *(const uint32_t*)&As[am + gid    ][2 * tk + 8];
            const uint32_t a3 = *(const uint32_t*)&As[am + gid + 8][2 * tk + 8];
            #pragma unroll
            for (int ni = 0; ni < 4; ni++)
                mma_fp16(acc[mi][ni], a0, a1, a2, a3, bf[ni][0], bf[ni][1]);
        }
        __syncthreads();
    }

    #pragma unroll
    for (int mi = 0; mi < 4; mi++) {
        #pragma unroll
        for (int ni = 0; ni < 4; ni++) {
            const int col = n0 + wn + ni * 8 + 2 * tk;
            const float b0v = bias[col], b1v = bias[col + 1];
            const int r0 = m0 + wm + mi * 16 + gid;
            const int r1 = r0 + 8;
            if (r0 < M_)
                *(float2*)(out + (size_t)r0 * D_ + col) =
                    make_float2(acc[mi][ni][0] + b0v, acc[mi][ni][1] + b1v);
            if (r1 < M_)
                *(float2*)(out + (size_t)r1 * D_ + col) =
                    make_float2(acc[mi][ni][2] + b0v, acc[mi][ni][3] + b1v);
        }
    }
}

// ---------------------------------------------------------------------------
// Fused attention, 32-row q tile (tf32, unchanged from R5):
//   scores strip (32x626) -> SMEM P -> softmax (+row0 fix, contrib capture)
//   -> probs written once -> ctx = P @ V from SMEM.
// ---------------------------------------------------------------------------
__global__ __launch_bounds__(256) void fused_attn(
    float* __restrict__ probs, const int* __restrict__ mask)
{
    extern __shared__ float sm[];
    float*    P  = sm;                                   // [QT][PSTR]
    uint32_t* Qs = (uint32_t*)(sm + QT * PSTR);          // [QT][QSTR]
    uint32_t* KV = Qs + QT * QSTR;                       // K [64][QSTR] / V [64][VSTR]

    const int bh  = blockIdx.y;
    const int m0  = blockIdx.x * QT;
    const int tid = threadIdx.x;
    const int wid = tid >> 5, lane = tid & 31;
    const int gid = lane >> 2, tk = lane & 3;
    const int wm  = (wid & 1) * 16;     // 2 warps along m (16 rows each)
    const int wn  = (wid >> 1) * 16;    // 4 warps along n (16 cols each)
    const int b   = bh / H_;
    const int h   = bh - b * H_;

    const float* qb = g_q + (size_t)bh * S_ * HD_;
    const float* kb = g_k + (size_t)bh * S_ * HD_;
    const float* vb = g_v + (size_t)bh * S_ * HD_;
    float* pgm = probs + (size_t)bh * S_ * S_;

    // zero pad columns 626..PSTR-1
    for (int i = tid; i < QT * (PSTR - S_); i += 256) {
        const int r = i / (PSTR - S_);
        const int c = S_ + i - r * (PSTR - S_);
        P[r * PSTR + c] = 0.f;
    }

    // load Q tile (QT rows x 64)
    #pragma unroll
    for (int i = 0; i < 2; i++) {
        const int idx = tid + i * 256;
        const int row = idx >> 4, c4 = (idx & 15) << 2;
        float4 v = make_float4(0.f, 0.f, 0.f, 0.f);
        if (m0 + row < S_) v = *(const float4*)(qb + (size_t)(m0 + row) * HD_ + c4);
        uint4 t;
        t.x = f2t(v.x); t.y = f2t(v.y); t.z = f2t(v.z); t.w = f2t(v.w);
        *(uint4*)&Qs[row * QSTR + c4] = t;
    }

    // ---- scores phase: P[QT][626] = (Q @ K^T) * 0.125 ----
    for (int nc = 0; nc < 10; nc++) {
        const int n0 = nc * 64;
        __syncthreads();
        #pragma unroll
        for (int i = 0; i < 4; i++) {
            const int idx = tid + i * 256;
            const int row = idx >> 4, c4 = (idx & 15) << 2;
            float4 v = make_float4(0.f, 0.f, 0.f, 0.f);
            if (n0 + row < S_) v = *(const float4*)(kb + (size_t)(n0 + row) * HD_ + c4);
            uint4 t;
            t.x = f2t(v.x); t.y = f2t(v.y); t.z = f2t(v.z); t.w = f2t(v.w);
            *(uint4*)&KV[row * QSTR + c4] = t;
        }
        __syncthreads();

        float acc[2][4];
        #pragma unroll
        for (int ni = 0; ni < 2; ni++)
            #pragma unroll
            for (int r = 0; r < 4; r++) acc[ni][r] = 0.f;

        #pragma unroll
        for (int ks = 0; ks < 64; ks += 8) {
            const uint32_t a0 = Qs[(wm + gid    ) * QSTR + ks + tk];
            const uint32_t a1 = Qs[(wm + gid + 8) * QSTR + ks + tk];
            const uint32_t a2 = Qs[(wm + gid    ) * QSTR + ks + tk + 4];
            const uint32_t a3 = Qs[(wm + gid + 8) * QSTR + ks + tk + 4];
            #pragma unroll
            for (int ni = 0; ni < 2; ni++) {
                const int nb = wn + ni * 8 + gid;
                mma_tf32(acc[ni], a0, a1, a2, a3,
                         KV[nb * QSTR + ks + tk], KV[nb * QSTR + ks + tk + 4]);
            }
        }

        #pragma unroll
        for (int ni = 0; ni < 2; ni++) {
            const int col = n0 + wn + ni * 8 + 2 * tk;   // even
            if (col < S_) {
                *(float2*)&P[(wm + gid    ) * PSTR + col] =
                    make_float2(acc[ni][0] * 0.125f, acc[ni][1] * 0.125f);
                *(float2*)&P[(wm + gid + 8) * PSTR + col] =
                    make_float2(acc[ni][2] * 0.125f, acc[ni][3] * 0.125f);
            }
        }
    }
    __syncthreads();

    // ---- softmax phase: warp w owns rows w*4..w*4+3 ----
    for (int r = wid * 4; r < wid * 4 + 4; r++) {
        const int q = m0 + r;
        if (q >= S_) break;
        float* row = P + r * PSTR;

        float mx = -3.4e38f;
        for (int i = lane; i < S_; i += 32) mx = fmaxf(mx, row[i]);
        #pragma unroll
        for (int o = 16; o; o >>= 1) mx = fmaxf(mx, __shfl_xor_sync(0xffffffffu, mx, o));

        if (q == 0) {
            const float add = mx * 0.25f;
            for (int i = lane; i < S_; i += 32) {
                const int mk = (i == 0) ? 0 : mask[b * SM1_ + i - 1];
                if (mk == 0) row[i] += add;
            }
            __syncwarp();
            mx = -3.4e38f;
            for (int i = lane; i < S_; i += 32) mx = fmaxf(mx, row[i]);
            #pragma unroll
            for (int o = 16; o; o >>= 1) mx = fmaxf(mx, __shfl_xor_sync(0xffffffffu, mx, o));
        }

        if (lane == 0) g_contrib[(size_t)bh * S_ + q] = row[0];

        float s = 0.f;
        for (int i = lane; i < S_; i += 32) {
            const float e = expf(row[i] - mx);
            row[i] = e;
            s += e;
        }
        #pragma unroll
        for (int o = 16; o; o >>= 1) s += __shfl_xor_sync(0xffffffffu, s, o);
        const float inv = 1.0f / s;

        float* prow = pgm + (size_t)q * S_;
        for (int i = lane; i < S_; i += 32) {
            const float p = row[i] * inv;
            row[i] = p;
            prow[i] = p;
        }
    }
    __syncthreads();

    // ---- ctx phase: ctx[QT][64] = P[QT][626] @ V[626][64] ----
    float cacc[2][4];
    #pragma unroll
    for (int ni = 0; ni < 2; ni++)
        #pragma unroll
        for (int r = 0; r < 4; r++) cacc[ni][r] = 0.f;

    for (int kc = 0; kc < 10; kc++) {
        const int k0 = kc * 64;
        __syncthreads();
        #pragma unroll
        for (int i = 0; i < 4; i++) {
            const int idx = tid + i * 256;
            const int row = idx >> 4, c4 = (idx & 15) << 2;
            float4 v = make_float4(0.f, 0.f, 0.f, 0.f);
            if (k0 + row < S_) v = *(const float4*)(vb + (size_t)(k0 + row) * HD_ + c4);
            uint4 t;
            t.x = f2t(v.x); t.y = f2t(v.y); t.z = f2t(v.z); t.w = f2t(v.w);
            *(uint4*)&KV[row * VSTR + c4] = t;
        }
        __syncthreads();

        #pragma unroll
        for (int ks = 0; ks < 64; ks += 8) {
            const uint32_t a0 = f2t(P[(wm + gid    ) * PSTR + k0 + ks + tk]);
            const uint32_t a1 = f2t(P[(wm + gid + 8) * PSTR + k0 + ks + tk]);
            const uint32_t a2 = f2t(P[(wm + gid    ) * PSTR + k0 + ks + tk + 4]);
            const uint32_t a3 = f2t(P[(wm + gid + 8) * PSTR + k0 + ks + tk + 4]);
            #pragma unroll
            for (int ni = 0; ni < 2; ni++) {
                mma_tf32(cacc[ni], a0, a1, a2, a3,
                         KV[(ks + tk    ) * VSTR + wn + ni * 8 + gid],
                         KV[(ks + tk + 4) * VSTR + wn + ni * 8 + gid]);
            }
        }
    }

    #pragma unroll
    for (int ni = 0; ni < 2; ni++) {
        const int col = wn + ni * 8 + 2 * tk;   // 0..62
        const int r0 = m0 + wm + gid;
        const int r1 = r0 + 8;
        if (r0 < S_)
            *(float2*)(g_ctx + ((size_t)(b * S_ + r0)) * D_ + h * HD_ + col) =
                make_float2(cacc[ni][0], cacc[ni][1]);
        if (r1 < S_)
            *(float2*)(g_ctx + ((size_t)(b * S_ + r1)) * D_ + h * HD_ + col) =
                make_float2(cacc[ni][2], cacc[ni][3]);
    }
}

// ---------------------------------------------------------------------------
// Contribution: softmax over q of g_contrib[bh, :]
// ---------------------------------------------------------------------------
__global__ __launch_bounds__(256) void contrib_kernel(float* __restrict__ out)
{
    const int bh = blockIdx.x;
    const float* src = g_contrib + (size_t)bh * S_;
    __shared__ float red[8];
    const int tid = threadIdx.x;

    float m = -3.4e38f;
    for (int i = tid; i < S_; i += 256) m = fmaxf(m, src[i]);
    #pragma unroll
    for (int o = 16; o; o >>= 1) m = fmaxf(m, __shfl_xor_sync(0xffffffffu, m, o));
    if ((tid & 31) == 0) red[tid >> 5] = m;
    __syncthreads();
    if (tid == 0) {
        float mm = red[0];
        #pragma unroll
        for (int w = 1; w < 8; w++) mm = fmaxf(mm, red[w]);
        red[0] = mm;
    }
    __syncthreads();
    m = red[0];
    __syncthreads();

    float s = 0.f;
    for (int i = tid; i < S_; i += 256) s += expf(src[i] - m);
    #pragma unroll
    for (int o = 16; o; o >>= 1) s += __shfl_xor_sync(0xffffffffu, s, o);
    if ((tid & 31) == 0) red[tid >> 5] = s;
    __syncthreads();
    if (tid == 0) {
        float ss = 0.f;
        #pragma unroll
        for (int w = 0; w < 8; w++) ss += red[w];
        red[0] = ss;
    }
    __syncthreads();
    const float inv = 1.0f / red[0];
    for (int i = tid; i < S_; i += 256)
        out[(size_t)bh * S_ + i] = expf(src[i] - m) * inv;
}

// ---------------------------------------------------------------------------
// Launch
// ---------------------------------------------------------------------------
extern "C" void kernel_launch(void* const* d_in, const int* in_sizes, int n_in,
                              void* d_out, int out_size)
{
    const float* hs = (const float*)d_in[0];
    const int*  mask = (const int*) d_in[1];
    const float* Wq = (const float*)d_in[2];
    const float* bq = (const float*)d_in[3];
    const float* Wk = (const float*)d_in[4];
    const float* bk = (const float*)d_in[5];
    const float* Wv = (const float*)d_in[6];
    const float* bv = (const float*)d_in[7];
    const float* Wo = (const float*)d_in[8];
    const float* bo = (const float*)d_in[9];

    float* out     = (float*)d_out;
    float* att_out = out;                                       // [B,S,D]
    float* probs   = out + (size_t)M_ * D_;                     // [B,H,S,S]
    float* contrib = probs + (size_t)BH_ * S_ * S_;             // [B,H,S]

    const int smem_bytes = (QT * PSTR + QT * QSTR + 64 * VSTR) * 4;
    cudaFuncSetAttribute(fused_attn,
        cudaFuncAttributeMaxDynamicSharedMemorySize, smem_bytes);

    gemm_qkv<<<dim3(79, 18), 256>>>(hs, Wq, bq, Wk, bk, Wv, bv);
    fused_attn<<<dim3(20, 192), 256, smem_bytes>>>(probs, mask);
    contrib_kernel<<<BH_, 256>>>(contrib);
    gemm_out<<<dim3(79, 6), 256>>>(Wo, bo, att_out);
}

// round 8
// speedup vs baseline: 1.2604x; 1.2604x over previous
#include <cuda_runtime.h>
#include <cuda_fp16.h>
#include <cstdint>

// Problem constants
#define B_   16
#define S_   626
#define D_   768
#define H_   12
#define HD_  64
#define M_   (B_*S_)          // 10016
#define BH_  (B_*H_)          // 192
#define SM1_ (S_-1)           // 625
#define PSTR 644              // P row stride (floats)
#define QSTR 68               // Q/K tile row stride (floats)
#define VSTR 72               // V tile row stride
#define QT   32               // q-tile rows in fused_attn
#define AST  24               // A tile k-stride (halves), LDSM conflict-free
#define BST  136              // B tile n-stride (halves), LDSM conflict-free

// Scratch (device globals; no cudaMalloc allowed)
__device__ float g_q[BH_*(size_t)S_*HD_];     // [b,h,s,hd]
__device__ float g_k[BH_*(size_t)S_*HD_];
__device__ float g_v[BH_*(size_t)S_*HD_];
__device__ float g_ctx[(size_t)M_*D_];        // [b,s, h*64+hd]
__device__ float g_contrib[BH_*S_];           // fixed scores col 0

// ---------------------------------------------------------------------------
// helpers
// ---------------------------------------------------------------------------
__device__ __forceinline__ uint32_t f2t(float x) {
    uint32_t r;
    asm("cvt.rna.tf32.f32 %0, %1;" : "=r"(r) : "f"(x));
    return r;
}

__device__ __forceinline__ void mma_tf32(float c[4],
    uint32_t a0, uint32_t a1, uint32_t a2, uint32_t a3,
    uint32_t b0, uint32_t b1)
{
    asm volatile(
        "mma.sync.aligned.m16n8k8.row.col.f32.tf32.tf32.f32 "
        "{%0,%1,%2,%3}, {%4,%5,%6,%7}, {%8,%9}, {%0,%1,%2,%3};"
        : "+f"(c[0]), "+f"(c[1]), "+f"(c[2]), "+f"(c[3])
        : "r"(a0), "r"(a1), "r"(a2), "r"(a3), "r"(b0), "r"(b1));
}

__device__ __forceinline__ void hmma(float c[4],
    uint32_t a0, uint32_t a1, uint32_t a2, uint32_t a3,
    uint32_t b0, uint32_t b1)
{
    asm volatile(
        "mma.sync.aligned.m16n8k16.row.col.f32.f16.f16.f32 "
        "{%0,%1,%2,%3}, {%4,%5,%6,%7}, {%8,%9}, {%0,%1,%2,%3};"
        : "+f"(c[0]), "+f"(c[1]), "+f"(c[2]), "+f"(c[3])
        : "r"(a0), "r"(a1), "r"(a2), "r"(a3), "r"(b0), "r"(b1));
}

__device__ __forceinline__ void ldsm_x4(
    uint32_t& r0, uint32_t& r1, uint32_t& r2, uint32_t& r3, const void* p)
{
    uint32_t a = (uint32_t)__cvta_generic_to_shared(p);
    asm volatile("ldmatrix.sync.aligned.m8n8.x4.shared.b16 {%0,%1,%2,%3}, [%4];"
        : "=r"(r0), "=r"(r1), "=r"(r2), "=r"(r3) : "r"(a));
}

__device__ __forceinline__ void ldsm_x4_t(
    uint32_t& r0, uint32_t& r1, uint32_t& r2, uint32_t& r3, const void* p)
{
    uint32_t a = (uint32_t)__cvta_generic_to_shared(p);
    asm volatile("ldmatrix.sync.aligned.m8n8.x4.trans.shared.b16 {%0,%1,%2,%3}, [%4];"
        : "=r"(r0), "=r"(r1), "=r"(r2), "=r"(r3) : "r"(a));
}

__device__ __forceinline__ uint4 pack8h(float4 a, float4 b) {
    uint4 u;
    __half2 h;
    h = __floats2half2_rn(a.x, a.y); u.x = *(uint32_t*)&h;
    h = __floats2half2_rn(a.z, a.w); u.y = *(uint32_t*)&h;
    h = __floats2half2_rn(b.x, b.y); u.z = *(uint32_t*)&h;
    h = __floats2half2_rn(b.z, b.w); u.w = *(uint32_t*)&h;
    return u;
}

// ---------------------------------------------------------------------------
// Projection GEMM core (fp16 m16n8k16 + ldmatrix, 1 sync/iter).
// Block 128x128, BK=16, 256 threads, warp tile 64x32. C = A[M,768]@W + bias.
// ---------------------------------------------------------------------------
template <bool QKV>
__device__ __forceinline__ void gemm_core(
    const float* __restrict__ Asrc, const float* __restrict__ W,
    const float* __restrict__ bias, float* __restrict__ dst,
    int m0, int n0,
    __half (*As)[128][AST], __half (*Bs)[16][BST])
{
    const int tid = threadIdx.x;
    const int wid = tid >> 5, lane = tid & 31;
    const int gid = lane >> 2, tk = lane & 3;
    const int wm = (wid & 1) * 64;
    const int wn = (wid >> 1) * 32;
    const int l15 = lane & 15, lhi = (lane >> 4) * 8;

    // tile-fill thread mapping
    const int arow = tid >> 1, ak8 = (tid & 1) * 8;   // A: [row][ak8..+7]
    const int bkr  = tid >> 4, bn8 = (tid & 15) * 8;  // B: [kr][bn8..+7]
    const bool aval = (m0 + arow < M_);

    float acc[4][4][4];
    #pragma unroll
    for (int mi = 0; mi < 4; mi++)
        #pragma unroll
        for (int ni = 0; ni < 4; ni++)
            #pragma unroll
            for (int r = 0; r < 4; r++) acc[mi][ni][r] = 0.f;

    // prologue: fill stage 0
    {
        float4 va0 = make_float4(0,0,0,0), va1 = make_float4(0,0,0,0);
        if (aval) {
            va0 = *(const float4*)(Asrc + (size_t)(m0 + arow) * D_ + ak8);
            va1 = *(const float4*)(Asrc + (size_t)(m0 + arow) * D_ + ak8 + 4);
        }
        float4 vb0 = *(const float4*)(W + (size_t)bkr * D_ + n0 + bn8);
        float4 vb1 = *(const float4*)(W + (size_t)bkr * D_ + n0 + bn8 + 4);
        *(uint4*)&As[0][arow][ak8] = pack8h(va0, va1);
        *(uint4*)&Bs[0][bkr][bn8]  = pack8h(vb0, vb1);
    }
    __syncthreads();

    const int NK = D_ / 16;   // 48
    for (int kt = 0; kt < NK; kt++) {
        const int cur = kt & 1;
        const bool pf = (kt + 1 < NK);
        float4 va0, va1, vb0, vb1;
        if (pf) {
            const int k1 = (kt + 1) * 16;
            va0 = va1 = make_float4(0,0,0,0);
            if (aval) {
                va0 = *(const float4*)(Asrc + (size_t)(m0 + arow) * D_ + k1 + ak8);
                va1 = *(const float4*)(Asrc + (size_t)(m0 + arow) * D_ + k1 + ak8 + 4);
            }
            vb0 = *(const float4*)(W + (size_t)(k1 + bkr) * D_ + n0 + bn8);
            vb1 = *(const float4*)(W + (size_t)(k1 + bkr) * D_ + n0 + bn8 + 4);
        }

        // fragments via ldmatrix
        uint32_t af[4][4];
        #pragma unroll
        for (int mi = 0; mi < 4; mi++)
            ldsm_x4(af[mi][0], af[mi][1], af[mi][2], af[mi][3],
                    &As[cur][wm + mi * 16 + l15][lhi]);
        uint32_t bf[8];
        ldsm_x4_t(bf[0], bf[1], bf[2], bf[3], &Bs[cur][l15][wn + lhi]);
        ldsm_x4_t(bf[4], bf[5], bf[6], bf[7], &Bs[cur][l15][wn + 16 + lhi]);

        #pragma unroll
        for (int mi = 0; mi < 4; mi++) {
            hmma(acc[mi][0], af[mi][0], af[mi][1], af[mi][2], af[mi][3], bf[0], bf[1]);
            hmma(acc[mi][1], af[mi][0], af[mi][1], af[mi][2], af[mi][3], bf[2], bf[3]);
            hmma(acc[mi][2], af[mi][0], af[mi][1], af[mi][2], af[mi][3], bf[4], bf[5]);
            hmma(acc[mi][3], af[mi][0], af[mi][1], af[mi][2], af[mi][3], bf[6], bf[7]);
        }

        if (pf) {
            *(uint4*)&As[cur ^ 1][arow][ak8] = pack8h(va0, va1);
            *(uint4*)&Bs[cur ^ 1][bkr][bn8]  = pack8h(vb0, vb1);
        }
        __syncthreads();
    }

    // epilogue
    #pragma unroll
    for (int mi = 0; mi < 4; mi++) {
        #pragma unroll
        for (int ni = 0; ni < 4; ni++) {
            const int col = n0 + wn + ni * 8 + 2 * tk;
            const float b0v = bias[col], b1v = bias[col + 1];
            const int r0 = m0 + wm + mi * 16 + gid;
            const int r1 = r0 + 8;
            if (QKV) {
                const int h = col >> 6, hd = col & 63;
                if (r0 < M_) {
                    const int b = r0 / S_, s = r0 - b * S_;
                    *(float2*)(dst + (((size_t)(b * H_ + h)) * S_ + s) * HD_ + hd) =
                        make_float2(acc[mi][ni][0] + b0v, acc[mi][ni][1] + b1v);
                }
                if (r1 < M_) {
                    const int b = r1 / S_, s = r1 - b * S_;
                    *(float2*)(dst + (((size_t)(b * H_ + h)) * S_ + s) * HD_ + hd) =
                        make_float2(acc[mi][ni][2] + b0v, acc[mi][ni][3] + b1v);
                }
            } else {
                if (r0 < M_)
                    *(float2*)(dst + (size_t)r0 * D_ + col) =
                        make_float2(acc[mi][ni][0] + b0v, acc[mi][ni][1] + b1v);
                if (r1 < M_)
                    *(float2*)(dst + (size_t)r1 * D_ + col) =
                        make_float2(acc[mi][ni][2] + b0v, acc[mi][ni][3] + b1v);
            }
        }
    }
}

__global__ __launch_bounds__(256, 2) void gemm_qkv(
    const float* __restrict__ X,
    const float* __restrict__ Wq, const float* __restrict__ bq,
    const float* __restrict__ Wk, const float* __restrict__ bk,
    const float* __restrict__ Wv, const float* __restrict__ bv)
{
    __shared__ __align__(16) __half As[2][128][AST];
    __shared__ __align__(16) __half Bs[2][16][BST];
    const int m0  = blockIdx.x * 128;
    const int ng  = blockIdx.y * 128;
    const int mat = ng / D_;
    const int n0  = ng - mat * D_;
    const float* W    = (mat == 0) ? Wq : (mat == 1) ? Wk : Wv;
    const float* bias = (mat == 0) ? bq : (mat == 1) ? bk : bv;
    float* dst        = (mat == 0) ? g_q : (mat == 1) ? g_k : g_v;
    gemm_core<true>(X, W, bias, dst, m0, n0, As, Bs);
}

__global__ __launch_bounds__(256, 2) void gemm_out(
    const float* __restrict__ W, const float* __restrict__ bias,
    float* __restrict__ out)
{
    __shared__ __align__(16) __half As[2][128][AST];
    __shared__ __align__(16) __half Bs[2][16][BST];
    gemm_core<false>(g_ctx, W, bias, out, blockIdx.x * 128, blockIdx.y * 128, As, Bs);
}

// ---------------------------------------------------------------------------
// Fused attention, 32-row q tile (tf32, unchanged from R5 — proven):
// ---------------------------------------------------------------------------
__global__ __launch_bounds__(256) void fused_attn(
    float* __restrict__ probs, const int* __restrict__ mask)
{
    extern __shared__ float sm[];
    float*    P  = sm;                                   // [QT][PSTR]
    uint32_t* Qs = (uint32_t*)(sm + QT * PSTR);          // [QT][QSTR]
    uint32_t* KV = Qs + QT * QSTR;                       // K [64][QSTR] / V [64][VSTR]

    const int bh  = blockIdx.y;
    const int m0  = blockIdx.x * QT;
    const int tid = threadIdx.x;
    const int wid = tid >> 5, lane = tid & 31;
    const int gid = lane >> 2, tk = lane & 3;
    const int wm  = (wid & 1) * 16;
    const int wn  = (wid >> 1) * 16;
    const int b   = bh / H_;
    const int h   = bh - b * H_;

    const float* qb = g_q + (size_t)bh * S_ * HD_;
    const float* kb = g_k + (size_t)bh * S_ * HD_;
    const float* vb = g_v + (size_t)bh * S_ * HD_;
    float* pgm = probs + (size_t)bh * S_ * S_;

    for (int i = tid; i < QT * (PSTR - S_); i += 256) {
        const int r = i / (PSTR - S_);
        const int c = S_ + i - r * (PSTR - S_);
        P[r * PSTR + c] = 0.f;
    }

    #pragma unroll
    for (int i = 0; i < 2; i++) {
        const int idx = tid + i * 256;
        const int row = idx >> 4, c4 = (idx & 15) << 2;
        float4 v = make_float4(0.f, 0.f, 0.f, 0.f);
        if (m0 + row < S_) v = *(const float4*)(qb + (size_t)(m0 + row) * HD_ + c4);
        uint4 t;
        t.x = f2t(v.x); t.y = f2t(v.y); t.z = f2t(v.z); t.w = f2t(v.w);
        *(uint4*)&Qs[row * QSTR + c4] = t;
    }

    for (int nc = 0; nc < 10; nc++) {
        const int n0 = nc * 64;
        __syncthreads();
        #pragma unroll
        for (int i = 0; i < 4; i++) {
            const int idx = tid + i * 256;
            const int row = idx >> 4, c4 = (idx & 15) << 2;
            float4 v = make_float4(0.f, 0.f, 0.f, 0.f);
            if (n0 + row < S_) v = *(const float4*)(kb + (size_t)(n0 + row) * HD_ + c4);
            uint4 t;
            t.x = f2t(v.x); t.y = f2t(v.y); t.z = f2t(v.z); t.w = f2t(v.w);
            *(uint4*)&KV[row * QSTR + c4] = t;
        }
        __syncthreads();

        float acc[2][4];
        #pragma unroll
        for (int ni = 0; ni < 2; ni++)
            #pragma unroll
            for (int r = 0; r < 4; r++) acc[ni][r] = 0.f;

        #pragma unroll
        for (int ks = 0; ks < 64; ks += 8) {
            const uint32_t a0 = Qs[(wm + gid    ) * QSTR + ks + tk];
            const uint32_t a1 = Qs[(wm + gid + 8) * QSTR + ks + tk];
            const uint32_t a2 = Qs[(wm + gid    ) * QSTR + ks + tk + 4];
            const uint32_t a3 = Qs[(wm + gid + 8) * QSTR + ks + tk + 4];
            #pragma unroll
            for (int ni = 0; ni < 2; ni++) {
                const int nb = wn + ni * 8 + gid;
                mma_tf32(acc[ni], a0, a1, a2, a3,
                         KV[nb * QSTR + ks + tk], KV[nb * QSTR + ks + tk + 4]);
            }
        }

        #pragma unroll
        for (int ni = 0; ni < 2; ni++) {
            const int col = n0 + wn + ni * 8 + 2 * tk;
            if (col < S_) {
                *(float2*)&P[(wm + gid    ) * PSTR + col] =
                    make_float2(acc[ni][0] * 0.125f, acc[ni][1] * 0.125f);
                *(float2*)&P[(wm + gid + 8) * PSTR + col] =
                    make_float2(acc[ni][2] * 0.125f, acc[ni][3] * 0.125f);
            }
        }
    }
    __syncthreads();

    for (int r = wid * 4; r < wid * 4 + 4; r++) {
        const int q = m0 + r;
        if (q >= S_) break;
        float* row = P + r * PSTR;

        float mx = -3.4e38f;
        for (int i = lane; i < S_; i += 32) mx = fmaxf(mx, row[i]);
        #pragma unroll
        for (int o = 16; o; o >>= 1) mx = fmaxf(mx, __shfl_xor_sync(0xffffffffu, mx, o));

        if (q == 0) {
            const float add = mx * 0.25f;
            for (int i = lane; i < S_; i += 32) {
                const int mk = (i == 0) ? 0 : mask[b * SM1_ + i - 1];
                if (mk == 0) row[i] += add;
            }
            __syncwarp();
            mx = -3.4e38f;
            for (int i = lane; i < S_; i += 32) mx = fmaxf(mx, row[i]);
            #pragma unroll
            for (int o = 16; o; o >>= 1) mx = fmaxf(mx, __shfl_xor_sync(0xffffffffu, mx, o));
        }

        if (lane == 0) g_contrib[(size_t)bh * S_ + q] = row[0];

        float s = 0.f;
        for (int i = lane; i < S_; i += 32) {
            const float e = expf(row[i] - mx);
            row[i] = e;
            s += e;
        }
        #pragma unroll
        for (int o = 16; o; o >>= 1) s += __shfl_xor_sync(0xffffffffu, s, o);
        const float inv = 1.0f / s;

        float* prow = pgm + (size_t)q * S_;
        for (int i = lane; i < S_; i += 32) {
            const float p = row[i] * inv;
            row[i] = p;
            prow[i] = p;
        }
    }
    __syncthreads();

    float cacc[2][4];
    #pragma unroll
    for (int ni = 0; ni < 2; ni++)
        #pragma unroll
        for (int r = 0; r < 4; r++) cacc[ni][r] = 0.f;

    for (int kc = 0; kc < 10; kc++) {
        const int k0 = kc * 64;
        __syncthreads();
        #pragma unroll
        for (int i = 0; i < 4; i++) {
            const int idx = tid + i * 256;
            const int row = idx >> 4, c4 = (idx & 15) << 2;
            float4 v = make_float4(0.f, 0.f, 0.f, 0.f);
            if (k0 + row < S_) v = *(const float4*)(vb + (size_t)(k0 + row) * HD_ + c4);
            uint4 t;
            t.x = f2t(v.x); t.y = f2t(v.y); t.z = f2t(v.z); t.w = f2t(v.w);
            *(uint4*)&KV[row * VSTR + c4] = t;
        }
        __syncthreads();

        #pragma unroll
        for (int ks = 0; ks < 64; ks += 8) {
            const uint32_t a0 = f2t(P[(wm + gid    ) * PSTR + k0 + ks + tk]);
            const uint32_t a1 = f2t(P[(wm + gid + 8) * PSTR + k0 + ks + tk]);
            const uint32_t a2 = f2t(P[(wm + gid    ) * PSTR + k0 + ks + tk + 4]);
            const uint32_t a3 = f2t(P[(wm + gid + 8) * PSTR + k0 + ks + tk + 4]);
            #pragma unroll
            for (int ni = 0; ni < 2; ni++) {
                mma_tf32(cacc[ni], a0, a1, a2, a3,
                         KV[(ks + tk    ) * VSTR + wn + ni * 8 + gid],
                         KV[(ks + tk + 4) * VSTR + wn + ni * 8 + gid]);
            }
        }
    }

    #pragma unroll
    for (int ni = 0; ni < 2; ni++) {
        const int col = wn + ni * 8 + 2 * tk;
        const int r0 = m0 + wm + gid;
        const int r1 = r0 + 8;
        if (r0 < S_)
            *(float2*)(g_ctx + ((size_t)(b * S_ + r0)) * D_ + h * HD_ + col) =
                make_float2(cacc[ni][0], cacc[ni][1]);
        if (r1 < S_)
            *(float2*)(g_ctx + ((size_t)(b * S_ + r1)) * D_ + h * HD_ + col) =
                make_float2(cacc[ni][2], cacc[ni][3]);
    }
}

// ---------------------------------------------------------------------------
// Contribution: softmax over q of g_contrib[bh, :]
// ---------------------------------------------------------------------------
__global__ __launch_bounds__(256) void contrib_kernel(float* __restrict__ out)
{
    const int bh = blockIdx.x;
    const float* src = g_contrib + (size_t)bh * S_;
    __shared__ float red[8];
    const int tid = threadIdx.x;

    float m = -3.4e38f;
    for (int i = tid; i < S_; i += 256) m = fmaxf(m, src[i]);
    #pragma unroll
    for (int o = 16; o; o >>= 1) m = fmaxf(m, __shfl_xor_sync(0xffffffffu, m, o));
    if ((tid & 31) == 0) red[tid >> 5] = m;
    __syncthreads();
    if (tid == 0) {
        float mm = red[0];
        #pragma unroll
        for (int w = 1; w < 8; w++) mm = fmaxf(mm, red[w]);
        red[0] = mm;
    }
    __syncthreads();
    m = red[0];
    __syncthreads();

    float s = 0.f;
    for (int i = tid; i < S_; i += 256) s += expf(src[i] - m);
    #pragma unroll
    for (int o = 16; o; o >>= 1) s += __shfl_xor_sync(0xffffffffu, s, o);
    if ((tid & 31) == 0) red[tid >> 5] = s;
    __syncthreads();
    if (tid == 0) {
        float ss = 0.f;
        #pragma unroll
        for (int w = 0; w < 8; w++) ss += red[w];
        red[0] = ss;
    }
    __syncthreads();
    const float inv = 1.0f / red[0];
    for (int i = tid; i < S_; i += 256)
        out[(size_t)bh * S_ + i] = expf(src[i] - m) * inv;
}

// ---------------------------------------------------------------------------
// Launch
// ---------------------------------------------------------------------------
extern "C" void kernel_launch(void* const* d_in, const int* in_sizes, int n_in,
                              void* d_out, int out_size)
{
    const float* hs = (const float*)d_in[0];
    const int*  mask = (const int*) d_in[1];
    const float* Wq = (const float*)d_in[2];
    const float* bq = (const float*)d_in[3];
    const float* Wk = (const float*)d_in[4];
    const float* bk = (const float*)d_in[5];
    const float* Wv = (const float*)d_in[6];
    const float* bv = (const float*)d_in[7];
    const float* Wo = (const float*)d_in[8];
    const float* bo = (const float*)d_in[9];

    float* out     = (float*)d_out;
    float* att_out = out;                                       // [B,S,D]
    float* probs   = out + (size_t)M_ * D_;                     // [B,H,S,S]
    float* contrib = probs + (size_t)BH_ * S_ * S_;             // [B,H,S]

    const int smem_bytes = (QT * PSTR + QT * QSTR + 64 * VSTR) * 4;
    cudaFuncSetAttribute(fused_attn,
        cudaFuncAttributeMaxDynamicSharedMemorySize, smem_bytes);

    gemm_qkv<<<dim3(79, 18), 256>>>(hs, Wq, bq, Wk, bk, Wv, bv);
    fused_attn<<<dim3(20, 192), 256, smem_bytes>>>(probs, mask);
    contrib_kernel<<<BH_, 256>>>(contrib);
    gemm_out<<<dim3(79, 6), 256>>>(Wo, bo, att_out);
}